// round 10
// baseline (speedup 1.0000x reference)
#include <cuda_runtime.h>
#include <cuda_fp16.h>
#include <cstdint>

#define SS   2048
#define DQ   4096
#define DKV  1024
#define SCL  (0.08838834764831845f * 1.4426950408889634f)

// smem: 3 K/V stages (32KB each: K@+0, V@+16K), then P double buffer (16KB x2)
#define OFF_P  98304
#define SMEM_BYTES 131072

// fp16 K/V scratch: 4096 tokens x 1024 dims x 2B = 8MB each
__device__ uint4 g_kh[524288];
__device__ uint4 g_vh[524288];

__device__ __forceinline__ uint32_t smem_u32(const void* p) {
    uint32_t a;
    asm("{ .reg .u64 t; cvta.to.shared.u64 t, %1; cvt.u32.u64 %0, t; }" : "=r"(a) : "l"(p));
    return a;
}
__device__ __forceinline__ float fast_ex2(float x) {
    float y; asm("ex2.approx.ftz.f32 %0, %1;" : "=f"(y) : "f"(x)); return y;
}
__device__ __forceinline__ void ldsm_x4(uint32_t* r, uint32_t addr) {
    asm volatile("ldmatrix.sync.aligned.m8n8.x4.shared.b16 {%0,%1,%2,%3}, [%4];"
        : "=r"(r[0]), "=r"(r[1]), "=r"(r[2]), "=r"(r[3]) : "r"(addr));
}
__device__ __forceinline__ void ldsm_x4_t(uint32_t* r, uint32_t addr) {
    asm volatile("ldmatrix.sync.aligned.m8n8.x4.trans.shared.b16 {%0,%1,%2,%3}, [%4];"
        : "=r"(r[0]), "=r"(r[1]), "=r"(r[2]), "=r"(r[3]) : "r"(addr));
}
__device__ __forceinline__ void mma16816(float* d, const uint32_t* a, const uint32_t* b) {
    asm volatile("mma.sync.aligned.m16n8k16.row.col.f32.f16.f16.f32 "
        "{%0,%1,%2,%3},{%4,%5,%6,%7},{%8,%9},{%0,%1,%2,%3};"
        : "+f"(d[0]), "+f"(d[1]), "+f"(d[2]), "+f"(d[3])
        : "r"(a[0]), "r"(a[1]), "r"(a[2]), "r"(a[3]), "r"(b[0]), "r"(b[1]));
}
__device__ __forceinline__ uint32_t packh2(float a, float b) {
    __half2 h = __floats2half2_rn(a, b);
    return *(uint32_t*)&h;
}
__device__ __forceinline__ float h2sum(uint32_t u) {
    float2 f = __half22float2(*(__half2*)&u);
    return f.x + f.y;
}
__device__ __forceinline__ void bar_grp(int id) {
    asm volatile("bar.sync %0, 128;" :: "r"(id) : "memory");
}
__device__ __forceinline__ void cp16(uint32_t dst, const void* src) {
    asm volatile("cp.async.cg.shared.global [%0], [%1], 16;" :: "r"(dst), "l"(src));
}

// ---- K/V fp32 -> fp16 convert (one pass, 8 elems/thread/tensor) ----
__global__ void __launch_bounds__(256)
cvt_kv(const float* __restrict__ k, const float* __restrict__ v)
{
    size_t i = (size_t)blockIdx.x * 256 + threadIdx.x;   // 0..524287
    const float4* ks = (const float4*)k + 2 * i;
    float4 a = ks[0], c = ks[1];
    g_kh[i] = make_uint4(packh2(a.x, a.y), packh2(a.z, a.w),
                         packh2(c.x, c.y), packh2(c.z, c.w));
    const float4* vs = (const float4*)v + 2 * i;
    a = vs[0]; c = vs[1];
    g_vh[i] = make_uint4(packh2(a.x, a.y), packh2(a.z, a.w),
                         packh2(c.x, c.y), packh2(c.z, c.w));
}

// CTA: 4 heads x 32 tokens = 128 q-rows, 512 threads (16 warps), BN=64 keys/tile.
// QK: warp w -> rows (w>>2)*32 (M=32), keys (w&3)*16.
// PV: warp w -> rows (w>>2)*32, hd cols (w&3)*32..+31.
__global__ void __launch_bounds__(512, 1)
attn_hmma7(const float* __restrict__ q, float* __restrict__ out)
{
    extern __shared__ char sm[];
    const uint32_t sb = smem_u32(sm);

    const int tid  = threadIdx.x;
    const int warp = tid >> 5, lane = tid & 31;
    const int qb = 63 - (int)blockIdx.x;      // longest CTAs first
    const int kv = blockIdx.y, b = blockIdx.z;
    const int q0 = qb * 32;
    const int hbase = kv * 4;
    const int ntiles = (qb >> 1) + 1;
    const int rg = warp >> 2;                 // row-group == head_local (0..3)
    const int r0 = rg * 32;
    const int kb0 = (warp & 3) * 16;          // QK key base
    const int colq = warp & 3;                // PV col-quarter
    const int m  = lane >> 3;

    // ---- stage Q fp16 (pre-scaled) into stage-0/1 region, 256B rows, swizzled ----
    #pragma unroll
    for (int it = 0; it < 4; ++it) {
        int id  = tid + 512 * it;
        int row = id >> 4, c16 = id & 15;
        int token = q0 + (row & 31);
        int head  = hbase + (row >> 5);
        const float4* gp = (const float4*)(q + (size_t)(b * SS + token) * DQ
                                             + head * 128 + c16 * 8);
        float4 f0 = gp[0], f1 = gp[1];
        uint32_t h0 = packh2(f0.x * SCL, f0.y * SCL);
        uint32_t h1 = packh2(f0.z * SCL, f0.w * SCL);
        uint32_t h2 = packh2(f1.x * SCL, f1.y * SCL);
        uint32_t h3 = packh2(f1.z * SCL, f1.w * SCL);
        uint32_t addr = sb + row * 256 + ((c16 ^ (row & 7)) << 4);
        asm volatile("st.shared.v4.b32 [%0],{%1,%2,%3,%4};"
            :: "r"(addr), "r"(h0), "r"(h1), "r"(h2), "r"(h3));
    }
    __syncthreads();

    // ---- persistent Q fragments, M=32: qf[kstep][mh][4] (64 regs) ----
    uint32_t qf[8][2][4];
    #pragma unroll
    for (int mh = 0; mh < 2; ++mh) {
        int row = r0 + mh * 16 + (lane & 7) + ((lane >> 3) & 1) * 8;
        #pragma unroll
        for (int ks = 0; ks < 8; ++ks) {
            int chunk = ks * 2 + (lane >> 4);
            ldsm_x4(qf[ks][mh], sb + row * 256 + ((chunk ^ (row & 7)) << 4));
        }
    }
    __syncthreads();   // Q region free for cp.async stages

    // ---- cp.async one K/V tile into stage jt%3 (fp16 source, no regs held) ----
    auto issue = [&](int jt) {
        size_t base = ((size_t)(b * SS + jt * 64) * DKV + kv * 128) * 2;
        const char* gk = (const char*)g_kh + base;
        const char* gv = (const char*)g_vh + base;
        uint32_t st = sb + 32768u * (uint32_t)(jt % 3);
        #pragma unroll
        for (int i = 0; i < 2; ++i) {
            int idx = tid + 512 * i;
            int row = idx >> 4, c16 = idx & 15;
            uint32_t d = st + row * 256 + ((c16 ^ (row & 7)) << 4);
            size_t so = (size_t)row * (DKV * 2) + c16 * 16;
            cp16(d,         gk + so);
            cp16(d + 16384, gv + so);
        }
        asm volatile("cp.async.commit_group;" ::: "memory");
    };

    issue(0);
    if (1 < ntiles) issue(1);

    float o[2][4][4];                         // 32 regs
    #pragma unroll
    for (int mh = 0; mh < 2; ++mh)
        #pragma unroll
        for (int i = 0; i < 4; ++i)
            #pragma unroll
            for (int j = 0; j < 4; ++j) o[mh][i][j] = 0.0f;
    float lsum[2][2] = {{0.0f, 0.0f}, {0.0f, 0.0f}};

    for (int jt = 0; jt < ntiles; ++jt) {
        if (jt + 1 < ntiles) asm volatile("cp.async.wait_group 1;" ::: "memory");
        else                 asm volatile("cp.async.wait_group 0;" ::: "memory");
        __syncthreads();     // stage jt%3 visible CTA-wide

        const uint32_t sK = sb + 32768u * (uint32_t)(jt % 3);
        const uint32_t sV = sK + 16384;
        const uint32_t sP = sb + OFF_P + (jt & 1) * 16384;

        // ---- QK^T: M=32 x 16 keys (this warp's key-quarter) ----
        float s[2][2][4];
        #pragma unroll
        for (int n2 = 0; n2 < 2; ++n2)
            #pragma unroll
            for (int mh = 0; mh < 2; ++mh)
                #pragma unroll
                for (int j = 0; j < 4; ++j) s[n2][mh][j] = 0.0f;

        #pragma unroll
        for (int n2 = 0; n2 < 2; ++n2) {
            int kr = kb0 + n2 * 8 + (lane & 7);
            #pragma unroll
            for (int ks2 = 0; ks2 < 4; ++ks2) {
                uint32_t kb[4];
                int chunk = ks2 * 4 + m;
                ldsm_x4(kb, sK + kr * 256 + ((chunk ^ (kr & 7)) << 4));
                mma16816(s[n2][0], qf[2*ks2][0],   kb);
                mma16816(s[n2][0], qf[2*ks2+1][0], kb + 2);
                mma16816(s[n2][1], qf[2*ks2][1],   kb);
                mma16816(s[n2][1], qf[2*ks2+1][1], kb + 2);
            }
        }

        // ---- softmax (no-rescale, base-2) + P -> smem ----
        #pragma unroll
        for (int n2 = 0; n2 < 2; ++n2) {
            int ng = (kb0 >> 3) + n2;         // global 8-key chunk in tile (0..7)
            int kg = jt * 64 + kb0 + n2 * 8 + (lane & 3) * 2;
            #pragma unroll
            for (int mh = 0; mh < 2; ++mh) {
                int row0 = r0 + mh * 16 + (lane >> 2);
                int tok0 = q0 + mh * 16 + (lane >> 2);
                float p00 = (kg     <= tok0)     ? fast_ex2(s[n2][mh][0]) : 0.0f;
                float p01 = (kg + 1 <= tok0)     ? fast_ex2(s[n2][mh][1]) : 0.0f;
                float p10 = (kg     <= tok0 + 8) ? fast_ex2(s[n2][mh][2]) : 0.0f;
                float p11 = (kg + 1 <= tok0 + 8) ? fast_ex2(s[n2][mh][3]) : 0.0f;
                int r1 = row0 + 8;
                uint32_t a0 = sP + row0 * 128 + ((ng ^ (row0 & 7)) << 4) + (lane & 3) * 4;
                uint32_t a1 = sP + r1   * 128 + ((ng ^ (r1   & 7)) << 4) + (lane & 3) * 4;
                asm volatile("st.shared.b32 [%0], %1;" :: "r"(a0), "r"(packh2(p00, p01)));
                asm volatile("st.shared.b32 [%0], %1;" :: "r"(a1), "r"(packh2(p10, p11)));
            }
        }

        // ---- issue stage jt+2 (that buffer was consumed in iter jt-1) ----
        if (jt + 2 < ntiles) issue(jt + 2);

        bar_grp(rg + 1);   // row-group's 4 warps exchange P (128-thread barrier)

        // ---- PV: rows r0..r0+31 x cols colq*32..+31; l from pf ----
        #pragma unroll
        for (int ks2 = 0; ks2 < 4; ++ks2) {
            uint32_t pf[2][4];
            #pragma unroll
            for (int mh = 0; mh < 2; ++mh) {
                int row = r0 + mh * 16 + (lane & 7) + ((lane >> 3) & 1) * 8;
                int chunk = ks2 * 2 + (lane >> 4);
                ldsm_x4(pf[mh], sP + row * 128 + ((chunk ^ (row & 7)) << 4));
                lsum[mh][0] += h2sum(pf[mh][0]) + h2sum(pf[mh][2]);
                lsum[mh][1] += h2sum(pf[mh][1]) + h2sum(pf[mh][3]);
            }
            int Vrow = ks2 * 16 + (m & 1) * 8 + (lane & 7);
            #pragma unroll
            for (int p2o = 0; p2o < 2; ++p2o) {
                uint32_t vb[4];
                int chunk = colq * 4 + p2o * 2 + (m >> 1);
                ldsm_x4_t(vb, sV + Vrow * 256 + ((chunk ^ (Vrow & 7)) << 4));
                mma16816(o[0][p2o*2],     pf[0], vb);
                mma16816(o[0][p2o*2 + 1], pf[0], vb + 2);
                mma16816(o[1][p2o*2],     pf[1], vb);
                mma16816(o[1][p2o*2 + 1], pf[1], vb + 2);
            }
        }
    }

    // ---- epilogue ----
    #pragma unroll
    for (int mh = 0; mh < 2; ++mh) {
        float l0 = lsum[mh][0], l1 = lsum[mh][1];
        l0 += __shfl_xor_sync(0xffffffffu, l0, 1);
        l0 += __shfl_xor_sync(0xffffffffu, l0, 2);
        l1 += __shfl_xor_sync(0xffffffffu, l1, 1);
        l1 += __shfl_xor_sync(0xffffffffu, l1, 2);
        float inv0 = 1.0f / l0, inv1 = 1.0f / l1;

        int tok0 = q0 + mh * 16 + (lane >> 2);
        int head = hbase + rg;
        float* r0p = out + (size_t)(b * SS + tok0) * DQ + head * 128
                   + colq * 32 + (lane & 3) * 2;
        float* r1p = r0p + (size_t)8 * DQ;
        #pragma unroll
        for (int n2o = 0; n2o < 4; ++n2o) {
            *(float2*)(r0p + n2o * 8) =
                make_float2(o[mh][n2o][0] * inv0, o[mh][n2o][1] * inv0);
            *(float2*)(r1p + n2o * 8) =
                make_float2(o[mh][n2o][2] * inv1, o[mh][n2o][3] * inv1);
        }
    }
}

extern "C" void kernel_launch(void* const* d_in, const int* in_sizes, int n_in,
                              void* d_out, int out_size)
{
    const float* q = (const float*)d_in[0];
    const float* k = (const float*)d_in[1];
    const float* v = (const float*)d_in[2];
    float* out = (float*)d_out;

    cvt_kv<<<2048, 256>>>(k, v);

    cudaFuncSetAttribute(attn_hmma7,
                         cudaFuncAttributeMaxDynamicSharedMemorySize, SMEM_BYTES);
    dim3 grid(64, 8, 2);   // qb, kv, batch
    attn_hmma7<<<grid, 512, SMEM_BYTES>>>(q, out);
}

// round 11
// speedup vs baseline: 1.2202x; 1.2202x over previous
#include <cuda_runtime.h>
#include <cuda_fp16.h>
#include <cstdint>

#define SS   2048
#define DQ   4096
#define DKV  1024
#define SCL  (0.08838834764831845f * 1.4426950408889634f)

// smem: 3 K/V stages, 32KB each (K@+0, V@+16K). Q staged over stages 0-1.
#define SMEM_BYTES 98304

// fp16 K/V scratch: 4096 tokens x 1024 dims x 2B = 8MB each
__device__ uint4 g_kh[524288];
__device__ uint4 g_vh[524288];

__device__ __forceinline__ uint32_t smem_u32(const void* p) {
    uint32_t a;
    asm("{ .reg .u64 t; cvta.to.shared.u64 t, %1; cvt.u32.u64 %0, t; }" : "=r"(a) : "l"(p));
    return a;
}
__device__ __forceinline__ float fast_ex2(float x) {
    float y; asm("ex2.approx.ftz.f32 %0, %1;" : "=f"(y) : "f"(x)); return y;
}
__device__ __forceinline__ void ldsm_x4(uint32_t* r, uint32_t addr) {
    asm volatile("ldmatrix.sync.aligned.m8n8.x4.shared.b16 {%0,%1,%2,%3}, [%4];"
        : "=r"(r[0]), "=r"(r[1]), "=r"(r[2]), "=r"(r[3]) : "r"(addr));
}
__device__ __forceinline__ void ldsm_x4_t(uint32_t* r, uint32_t addr) {
    asm volatile("ldmatrix.sync.aligned.m8n8.x4.trans.shared.b16 {%0,%1,%2,%3}, [%4];"
        : "=r"(r[0]), "=r"(r[1]), "=r"(r[2]), "=r"(r[3]) : "r"(addr));
}
__device__ __forceinline__ void mma16816(float* d, const uint32_t* a, const uint32_t* b) {
    asm volatile("mma.sync.aligned.m16n8k16.row.col.f32.f16.f16.f32 "
        "{%0,%1,%2,%3},{%4,%5,%6,%7},{%8,%9},{%0,%1,%2,%3};"
        : "+f"(d[0]), "+f"(d[1]), "+f"(d[2]), "+f"(d[3])
        : "r"(a[0]), "r"(a[1]), "r"(a[2]), "r"(a[3]), "r"(b[0]), "r"(b[1]));
}
__device__ __forceinline__ uint32_t packh2(float a, float b) {
    __half2 h = __floats2half2_rn(a, b);
    return *(uint32_t*)&h;
}
__device__ __forceinline__ void cp16(uint32_t dst, const void* src) {
    asm volatile("cp.async.cg.shared.global [%0], [%1], 16;" :: "r"(dst), "l"(src));
}

// ---- K/V fp32 -> fp16 convert (one pass, 8 elems/thread/tensor) ----
__global__ void __launch_bounds__(256)
cvt_kv(const float* __restrict__ k, const float* __restrict__ v)
{
    size_t i = (size_t)blockIdx.x * 256 + threadIdx.x;   // 0..524287
    const float4* ks = (const float4*)k + 2 * i;
    float4 a = ks[0], c = ks[1];
    g_kh[i] = make_uint4(packh2(a.x, a.y), packh2(a.z, a.w),
                         packh2(c.x, c.y), packh2(c.z, c.w));
    const float4* vs = (const float4*)v + 2 * i;
    a = vs[0]; c = vs[1];
    g_vh[i] = make_uint4(packh2(a.x, a.y), packh2(a.z, a.w),
                         packh2(c.x, c.y), packh2(c.z, c.w));
}

// CTA: 4 heads x 32 tokens = 128 q-rows, 256 threads (8 warps), BN=64 keys/tile.
// Warp w: rows w*16..w*16+15 (head = w>>1, tokens q0 + (w&1)*16 ..).
// Each warp: S = Q(16xK) @ K^T(64 keys), exp in regs, O += P(reg) @ V (full hd).
// No P shared-memory roundtrip: QK C-fragments ARE the PV A-fragments.
__global__ void __launch_bounds__(256, 1)
attn_hmma8(const float* __restrict__ q, float* __restrict__ out)
{
    extern __shared__ char sm[];
    const uint32_t sb = smem_u32(sm);

    const int tid  = threadIdx.x;
    const int warp = tid >> 5, lane = tid & 31;
    const int qb = 63 - (int)blockIdx.x;      // longest CTAs first
    const int kv = blockIdx.y, b = blockIdx.z;
    const int q0 = qb * 32;
    const int hbase = kv * 4;
    const int ntiles = (qb >> 1) + 1;
    const int m  = lane >> 3;

    // ---- stage Q fp16 (pre-scaled) into stage-0/1 region, 256B rows, swizzled ----
    #pragma unroll
    for (int it = 0; it < 8; ++it) {
        int id  = tid + 256 * it;
        int row = id >> 4, c16 = id & 15;
        int token = q0 + (row & 31);
        int head  = hbase + (row >> 5);
        const float4* gp = (const float4*)(q + (size_t)(b * SS + token) * DQ
                                             + head * 128 + c16 * 8);
        float4 f0 = gp[0], f1 = gp[1];
        uint32_t h0 = packh2(f0.x * SCL, f0.y * SCL);
        uint32_t h1 = packh2(f0.z * SCL, f0.w * SCL);
        uint32_t h2 = packh2(f1.x * SCL, f1.y * SCL);
        uint32_t h3 = packh2(f1.z * SCL, f1.w * SCL);
        uint32_t addr = sb + row * 256 + ((c16 ^ (row & 7)) << 4);
        asm volatile("st.shared.v4.b32 [%0],{%1,%2,%3,%4};"
            :: "r"(addr), "r"(h0), "r"(h1), "r"(h2), "r"(h3));
    }
    __syncthreads();

    // ---- persistent Q fragments, M=16: qf[kstep][4] (32 regs) ----
    uint32_t qf[8][4];
    {
        int row = warp * 16 + (lane & 7) + ((lane >> 3) & 1) * 8;
        #pragma unroll
        for (int ks = 0; ks < 8; ++ks) {
            int chunk = ks * 2 + (lane >> 4);
            ldsm_x4(qf[ks], sb + row * 256 + ((chunk ^ (row & 7)) << 4));
        }
    }
    __syncthreads();   // Q region free for cp.async stages

    // ---- cp.async one K/V tile into stage jt%3 (fp16 source, no regs held) ----
    auto issue = [&](int jt) {
        size_t base = ((size_t)(b * SS + jt * 64) * DKV + kv * 128) * 2;
        const char* gk = (const char*)g_kh + base;
        const char* gv = (const char*)g_vh + base;
        uint32_t st = sb + 32768u * (uint32_t)(jt % 3);
        #pragma unroll
        for (int i = 0; i < 4; ++i) {
            int idx = tid + 256 * i;
            int row = idx >> 4, c16 = idx & 15;
            uint32_t d = st + row * 256 + ((c16 ^ (row & 7)) << 4);
            size_t so = (size_t)row * (DKV * 2) + c16 * 16;
            cp16(d,         gk + so);
            cp16(d + 16384, gv + so);
        }
        asm volatile("cp.async.commit_group;" ::: "memory");
    };

    issue(0);
    if (1 < ntiles) issue(1);

    float o[16][4];                           // 64 regs
    #pragma unroll
    for (int i = 0; i < 16; ++i)
        #pragma unroll
        for (int j = 0; j < 4; ++j) o[i][j] = 0.0f;
    float lsum0 = 0.0f, lsum1 = 0.0f;

    const int tok0 = q0 + (warp & 1) * 16 + (lane >> 2);

    for (int jt = 0; jt < ntiles; ++jt) {
        if (jt + 1 < ntiles) asm volatile("cp.async.wait_group 1;" ::: "memory");
        else                 asm volatile("cp.async.wait_group 0;" ::: "memory");
        __syncthreads();     // stage jt%3 visible CTA-wide (only barrier per tile)

        const uint32_t sK = sb + 32768u * (uint32_t)(jt % 3);
        const uint32_t sV = sK + 16384;

        // ---- QK^T: 16 rows x 64 keys, s[n2] = keys n2*8..+7 (fp32, 32 regs) ----
        float s[8][4];
        #pragma unroll
        for (int n2 = 0; n2 < 8; ++n2)
            #pragma unroll
            for (int j = 0; j < 4; ++j) s[n2][j] = 0.0f;

        #pragma unroll
        for (int n2 = 0; n2 < 8; ++n2) {
            int kr = n2 * 8 + (lane & 7);
            #pragma unroll
            for (int ks2 = 0; ks2 < 4; ++ks2) {
                uint32_t kb[4];
                int chunk = ks2 * 4 + m;
                ldsm_x4(kb, sK + kr * 256 + ((chunk ^ (kr & 7)) << 4));
                mma16816(s[n2], qf[2*ks2],     kb);
                mma16816(s[n2], qf[2*ks2+1],   kb + 2);
            }
        }

        // ---- softmax in registers (no-rescale, base-2, causal) ----
        #pragma unroll
        for (int n2 = 0; n2 < 8; ++n2) {
            int kg = jt * 64 + n2 * 8 + (lane & 3) * 2;
            s[n2][0] = (kg     <= tok0)     ? fast_ex2(s[n2][0]) : 0.0f;
            s[n2][1] = (kg + 1 <= tok0)     ? fast_ex2(s[n2][1]) : 0.0f;
            s[n2][2] = (kg     <= tok0 + 8) ? fast_ex2(s[n2][2]) : 0.0f;
            s[n2][3] = (kg + 1 <= tok0 + 8) ? fast_ex2(s[n2][3]) : 0.0f;
            lsum0 += s[n2][0] + s[n2][1];
            lsum1 += s[n2][2] + s[n2][3];
        }

        // ---- issue stage jt+2 (that buffer was consumed in iter jt-1) ----
        if (jt + 2 < ntiles) issue(jt + 2);

        // ---- PV: C->A register reuse, no smem for P ----
        #pragma unroll
        for (int ks2 = 0; ks2 < 4; ++ks2) {
            uint32_t pa[4];
            pa[0] = packh2(s[2*ks2][0],   s[2*ks2][1]);     // (r,    k 2c..2c+1)
            pa[1] = packh2(s[2*ks2][2],   s[2*ks2][3]);     // (r+8,  k 2c..2c+1)
            pa[2] = packh2(s[2*ks2+1][0], s[2*ks2+1][1]);   // (r,    k 8+2c..)
            pa[3] = packh2(s[2*ks2+1][2], s[2*ks2+1][3]);   // (r+8,  k 8+2c..)
            int Vrow = ks2 * 16 + (m & 1) * 8 + (lane & 7);
            #pragma unroll
            for (int n2o = 0; n2o < 16; n2o += 2) {
                uint32_t vb[4];
                int chunk = n2o + (m >> 1);
                ldsm_x4_t(vb, sV + Vrow * 256 + ((chunk ^ (Vrow & 7)) << 4));
                mma16816(o[n2o],     pa, vb);
                mma16816(o[n2o + 1], pa, vb + 2);
            }
        }
    }

    // ---- epilogue: reduce l over the 4 lanes sharing a row, normalize, store ----
    lsum0 += __shfl_xor_sync(0xffffffffu, lsum0, 1);
    lsum0 += __shfl_xor_sync(0xffffffffu, lsum0, 2);
    lsum1 += __shfl_xor_sync(0xffffffffu, lsum1, 1);
    lsum1 += __shfl_xor_sync(0xffffffffu, lsum1, 2);
    float inv0 = 1.0f / lsum0, inv1 = 1.0f / lsum1;

    const int head = hbase + (warp >> 1);
    float* r0p = out + (size_t)(b * SS + tok0) * DQ + head * 128 + (lane & 3) * 2;
    float* r1p = r0p + (size_t)8 * DQ;
    #pragma unroll
    for (int n2o = 0; n2o < 16; ++n2o) {
        *(float2*)(r0p + n2o * 8) =
            make_float2(o[n2o][0] * inv0, o[n2o][1] * inv0);
        *(float2*)(r1p + n2o * 8) =
            make_float2(o[n2o][2] * inv1, o[n2o][3] * inv1);
    }
}

extern "C" void kernel_launch(void* const* d_in, const int* in_sizes, int n_in,
                              void* d_out, int out_size)
{
    const float* q = (const float*)d_in[0];
    const float* k = (const float*)d_in[1];
    const float* v = (const float*)d_in[2];
    float* out = (float*)d_out;

    cvt_kv<<<2048, 256>>>(k, v);

    cudaFuncSetAttribute(attn_hmma8,
                         cudaFuncAttributeMaxDynamicSharedMemorySize, SMEM_BYTES);
    dim3 grid(64, 8, 2);   // qb, kv, batch
    attn_hmma8<<<grid, 256, SMEM_BYTES>>>(q, out);
}

// round 12
// speedup vs baseline: 1.2426x; 1.0183x over previous
#include <cuda_runtime.h>
#include <cuda_fp16.h>
#include <cstdint>

#define SS   2048
#define DQ   4096
#define DKV  1024
#define SCL  (0.08838834764831845f * 1.4426950408889634f)

// smem: 3 K/V stages, 32KB each (K@+0, V@+16K). Q staged over stages 0-1.
#define SMEM_BYTES 98304

// fp16 K/V scratch: 4096 tokens x 1024 dims x 2B = 8MB each
__device__ uint4 g_kh[524288];
__device__ uint4 g_vh[524288];

__device__ __forceinline__ uint32_t smem_u32(const void* p) {
    uint32_t a;
    asm("{ .reg .u64 t; cvta.to.shared.u64 t, %1; cvt.u32.u64 %0, t; }" : "=r"(a) : "l"(p));
    return a;
}
__device__ __forceinline__ float fast_ex2(float x) {
    float y; asm("ex2.approx.ftz.f32 %0, %1;" : "=f"(y) : "f"(x)); return y;
}
__device__ __forceinline__ void ldsm_x4(uint32_t* r, uint32_t addr) {
    asm volatile("ldmatrix.sync.aligned.m8n8.x4.shared.b16 {%0,%1,%2,%3}, [%4];"
        : "=r"(r[0]), "=r"(r[1]), "=r"(r[2]), "=r"(r[3]) : "r"(addr));
}
__device__ __forceinline__ void ldsm_x4_t(uint32_t* r, uint32_t addr) {
    asm volatile("ldmatrix.sync.aligned.m8n8.x4.trans.shared.b16 {%0,%1,%2,%3}, [%4];"
        : "=r"(r[0]), "=r"(r[1]), "=r"(r[2]), "=r"(r[3]) : "r"(addr));
}
__device__ __forceinline__ void mma16816(float* d, const uint32_t* a, const uint32_t* b) {
    asm volatile("mma.sync.aligned.m16n8k16.row.col.f32.f16.f16.f32 "
        "{%0,%1,%2,%3},{%4,%5,%6,%7},{%8,%9},{%0,%1,%2,%3};"
        : "+f"(d[0]), "+f"(d[1]), "+f"(d[2]), "+f"(d[3])
        : "r"(a[0]), "r"(a[1]), "r"(a[2]), "r"(a[3]), "r"(b[0]), "r"(b[1]));
}
__device__ __forceinline__ uint32_t packh2(float a, float b) {
    __half2 h = __floats2half2_rn(a, b);
    return *(uint32_t*)&h;
}
__device__ __forceinline__ void cp16(uint32_t dst, const void* src) {
    asm volatile("cp.async.cg.shared.global [%0], [%1], 16;" :: "r"(dst), "l"(src));
}

// ---- K/V fp32 -> fp16 convert (one pass, 8 elems/thread/tensor) ----
__global__ void __launch_bounds__(256)
cvt_kv(const float* __restrict__ k, const float* __restrict__ v)
{
    size_t i = (size_t)blockIdx.x * 256 + threadIdx.x;   // 0..524287
    const float4* ks = (const float4*)k + 2 * i;
    float4 a = ks[0], c = ks[1];
    g_kh[i] = make_uint4(packh2(a.x, a.y), packh2(a.z, a.w),
                         packh2(c.x, c.y), packh2(c.z, c.w));
    const float4* vs = (const float4*)v + 2 * i;
    a = vs[0]; c = vs[1];
    g_vh[i] = make_uint4(packh2(a.x, a.y), packh2(a.z, a.w),
                         packh2(c.x, c.y), packh2(c.z, c.w));
}

// CTA: 4 heads x 32 tokens = 128 q-rows, 256 threads (8 warps), BN=64 keys/tile.
// Warp w: rows w*16..w*16+15 (head = w>>1, tokens q0 + (w&1)*16 ..).
// Each warp: S = Q(16xK) @ K^T(64 keys), exp in regs, O += P(reg) @ V (full hd).
// No P shared-memory roundtrip: QK C-fragments ARE the PV A-fragments.
__global__ void __launch_bounds__(256, 1)
attn_hmma9(const float* __restrict__ q, float* __restrict__ out)
{
    extern __shared__ char sm[];
    const uint32_t sb = smem_u32(sm);

    const int tid  = threadIdx.x;
    const int warp = tid >> 5, lane = tid & 31;
    const int qb = 63 - (int)blockIdx.x;      // longest CTAs first
    const int kv = blockIdx.y, b = blockIdx.z;
    const int q0 = qb * 32;
    const int hbase = kv * 4;
    const int ntiles = (qb >> 1) + 1;
    const int m  = lane >> 3;

    // ---- stage Q fp16 (pre-scaled) into stage-0/1 region, 256B rows, swizzled ----
    #pragma unroll
    for (int it = 0; it < 8; ++it) {
        int id  = tid + 256 * it;
        int row = id >> 4, c16 = id & 15;
        int token = q0 + (row & 31);
        int head  = hbase + (row >> 5);
        const float4* gp = (const float4*)(q + (size_t)(b * SS + token) * DQ
                                             + head * 128 + c16 * 8);
        float4 f0 = gp[0], f1 = gp[1];
        uint32_t h0 = packh2(f0.x * SCL, f0.y * SCL);
        uint32_t h1 = packh2(f0.z * SCL, f0.w * SCL);
        uint32_t h2 = packh2(f1.x * SCL, f1.y * SCL);
        uint32_t h3 = packh2(f1.z * SCL, f1.w * SCL);
        uint32_t addr = sb + row * 256 + ((c16 ^ (row & 7)) << 4);
        asm volatile("st.shared.v4.b32 [%0],{%1,%2,%3,%4};"
            :: "r"(addr), "r"(h0), "r"(h1), "r"(h2), "r"(h3));
    }
    __syncthreads();

    // ---- persistent Q fragments, M=16: qf[kstep][4] (32 regs) ----
    uint32_t qf[8][4];
    {
        int row = warp * 16 + (lane & 7) + ((lane >> 3) & 1) * 8;
        #pragma unroll
        for (int ks = 0; ks < 8; ++ks) {
            int chunk = ks * 2 + (lane >> 4);
            ldsm_x4(qf[ks], sb + row * 256 + ((chunk ^ (row & 7)) << 4));
        }
    }
    __syncthreads();   // Q region free for cp.async stages

    // ---- cp.async one K/V tile into stage jt%3 (fp16 source, no regs held) ----
    auto issue = [&](int jt) {
        size_t base = ((size_t)(b * SS + jt * 64) * DKV + kv * 128) * 2;
        const char* gk = (const char*)g_kh + base;
        const char* gv = (const char*)g_vh + base;
        uint32_t st = sb + 32768u * (uint32_t)(jt % 3);
        #pragma unroll
        for (int i = 0; i < 4; ++i) {
            int idx = tid + 256 * i;
            int row = idx >> 4, c16 = idx & 15;
            uint32_t d = st + row * 256 + ((c16 ^ (row & 7)) << 4);
            size_t so = (size_t)row * (DKV * 2) + c16 * 16;
            cp16(d,         gk + so);
            cp16(d + 16384, gv + so);
        }
        asm volatile("cp.async.commit_group;" ::: "memory");
    };

    issue(0);
    if (1 < ntiles) issue(1);

    float o[16][4];                           // 64 regs
    #pragma unroll
    for (int i = 0; i < 16; ++i)
        #pragma unroll
        for (int j = 0; j < 4; ++j) o[i][j] = 0.0f;
    float lsum0 = 0.0f, lsum1 = 0.0f;

    const int tok0 = q0 + (warp & 1) * 16 + (lane >> 2);

    for (int jt = 0; jt < ntiles; ++jt) {
        if (jt + 1 < ntiles) asm volatile("cp.async.wait_group 1;" ::: "memory");
        else                 asm volatile("cp.async.wait_group 0;" ::: "memory");
        __syncthreads();     // stage jt%3 visible CTA-wide (only barrier per tile)

        const uint32_t sK = sb + 32768u * (uint32_t)(jt % 3);
        const uint32_t sV = sK + 16384;

        // ---- QK^T: ks2 outer, n2 inner -> 8 independent accumulator chains ----
        float s[8][4];
        #pragma unroll
        for (int n2 = 0; n2 < 8; ++n2)
            #pragma unroll
            for (int j = 0; j < 4; ++j) s[n2][j] = 0.0f;

        #pragma unroll
        for (int ks2 = 0; ks2 < 4; ++ks2) {
            #pragma unroll
            for (int n2 = 0; n2 < 8; ++n2) {
                uint32_t kb[4];
                int kr = n2 * 8 + (lane & 7);
                int chunk = ks2 * 4 + m;
                ldsm_x4(kb, sK + kr * 256 + ((chunk ^ (kr & 7)) << 4));
                mma16816(s[n2], qf[2*ks2],   kb);
                mma16816(s[n2], qf[2*ks2+1], kb + 2);
            }
        }

        // ---- softmax in regs + pack PV A-fragments (s dies, pa 16 regs) ----
        uint32_t pa[4][4];
        if (jt + 1 < ntiles) {
            // interior tile: no causal mask needed (all keys <= all tokens)
            #pragma unroll
            for (int n2 = 0; n2 < 8; ++n2) {
                float e0 = fast_ex2(s[n2][0]);
                float e1 = fast_ex2(s[n2][1]);
                float e2 = fast_ex2(s[n2][2]);
                float e3 = fast_ex2(s[n2][3]);
                lsum0 += e0 + e1;
                lsum1 += e2 + e3;
                pa[n2 >> 1][(n2 & 1) * 2]     = packh2(e0, e1);
                pa[n2 >> 1][(n2 & 1) * 2 + 1] = packh2(e2, e3);
            }
        } else {
            // diagonal tile: causal mask
            #pragma unroll
            for (int n2 = 0; n2 < 8; ++n2) {
                int kg = jt * 64 + n2 * 8 + (lane & 3) * 2;
                float e0 = (kg     <= tok0)     ? fast_ex2(s[n2][0]) : 0.0f;
                float e1 = (kg + 1 <= tok0)     ? fast_ex2(s[n2][1]) : 0.0f;
                float e2 = (kg     <= tok0 + 8) ? fast_ex2(s[n2][2]) : 0.0f;
                float e3 = (kg + 1 <= tok0 + 8) ? fast_ex2(s[n2][3]) : 0.0f;
                lsum0 += e0 + e1;
                lsum1 += e2 + e3;
                pa[n2 >> 1][(n2 & 1) * 2]     = packh2(e0, e1);
                pa[n2 >> 1][(n2 & 1) * 2 + 1] = packh2(e2, e3);
            }
        }

        // ---- issue stage jt+2 (that buffer was consumed in iter jt-1) ----
        if (jt + 2 < ntiles) issue(jt + 2);

        // ---- PV: C->A register reuse, no smem for P ----
        #pragma unroll
        for (int ks2 = 0; ks2 < 4; ++ks2) {
            int Vrow = ks2 * 16 + (m & 1) * 8 + (lane & 7);
            #pragma unroll
            for (int n2o = 0; n2o < 16; n2o += 2) {
                uint32_t vb[4];
                int chunk = n2o + (m >> 1);
                ldsm_x4_t(vb, sV + Vrow * 256 + ((chunk ^ (Vrow & 7)) << 4));
                mma16816(o[n2o],     pa[ks2], vb);
                mma16816(o[n2o + 1], pa[ks2], vb + 2);
            }
        }
    }

    // ---- epilogue: reduce l over the 4 lanes sharing a row, normalize, store ----
    lsum0 += __shfl_xor_sync(0xffffffffu, lsum0, 1);
    lsum0 += __shfl_xor_sync(0xffffffffu, lsum0, 2);
    lsum1 += __shfl_xor_sync(0xffffffffu, lsum1, 1);
    lsum1 += __shfl_xor_sync(0xffffffffu, lsum1, 2);
    float inv0 = 1.0f / lsum0, inv1 = 1.0f / lsum1;

    const int head = hbase + (warp >> 1);
    float* r0p = out + (size_t)(b * SS + tok0) * DQ + head * 128 + (lane & 3) * 2;
    float* r1p = r0p + (size_t)8 * DQ;
    #pragma unroll
    for (int n2o = 0; n2o < 16; ++n2o) {
        *(float2*)(r0p + n2o * 8) =
            make_float2(o[n2o][0] * inv0, o[n2o][1] * inv0);
        *(float2*)(r1p + n2o * 8) =
            make_float2(o[n2o][2] * inv1, o[n2o][3] * inv1);
    }
}

extern "C" void kernel_launch(void* const* d_in, const int* in_sizes, int n_in,
                              void* d_out, int out_size)
{
    const float* q = (const float*)d_in[0];
    const float* k = (const float*)d_in[1];
    const float* v = (const float*)d_in[2];
    float* out = (float*)d_out;

    cvt_kv<<<2048, 256>>>(k, v);

    cudaFuncSetAttribute(attn_hmma9,
                         cudaFuncAttributeMaxDynamicSharedMemorySize, SMEM_BYTES);
    dim3 grid(64, 8, 2);   // qb, kv, batch
    attn_hmma9<<<grid, 256, SMEM_BYTES>>>(q, out);
}